// round 16
// baseline (speedup 1.0000x reference)
#include <cuda_runtime.h>
#include <cuda_fp16.h>
#include <cstdint>

#define BB 16
#define SQ 2048
#define SK 2048
#define DD 64

#define QTILE 128
#define KTILE 64

// ---- smem layout (bytes) ----
#define SM_Q    0
#define SM_ST0  16384
#define ST_K    0
#define ST_V    8192
#define ST_SZ   16384
#define NSTAGE  3
#define SMEM_TOTAL (SM_ST0 + NSTAGE*ST_SZ)   // 65536

__device__ float    g_recip[BB * SQ];
__device__ int      g_cnt[BB];
__device__ uint32_t g_mbits[BB * 64];
__device__ int      g_cpf[BB * 64];
// unnormalized e (fp16) in MMA-FRAGMENT order (padded slots hold 1.0, never read):
// per (b, qblk): 65536 uint2; index = ((i*8 + w)*8 + n)*32 + lane
__device__ __half   g_ecomp[(size_t)BB * SQ * SK];
// pre-swizzled fp16 (128B/row). Q,K,V single fp16; K/V in compact order,
// padded slots ZEROED (=> s=0, e=1, PV contribution 0).
__device__ char g_qh[(size_t)BB * SQ * 128];
__device__ char g_kh[(size_t)BB * SK * 128], g_vh[(size_t)BB * SK * 128];

// ---------------------------------------------------------------------------
#define LDSM_X4(R, addr) \
    asm volatile("ldmatrix.sync.aligned.m8n8.x4.shared.b16 {%0,%1,%2,%3}, [%4];" \
        : "=r"((R)[0]), "=r"((R)[1]), "=r"((R)[2]), "=r"((R)[3]) : "r"(addr))
#define LDSM_X4T(R, addr) \
    asm volatile("ldmatrix.sync.aligned.m8n8.x4.trans.shared.b16 {%0,%1,%2,%3}, [%4];" \
        : "=r"((R)[0]), "=r"((R)[1]), "=r"((R)[2]), "=r"((R)[3]) : "r"(addr))

#define CPA16(dst, src) \
    asm volatile("cp.async.cg.shared.global [%0], [%1], 16;" :: "r"(dst), "l"(src))
#define CPCOMMIT() asm volatile("cp.async.commit_group;" ::: "memory")
#define CPWAIT1()  asm volatile("cp.async.wait_group 1;" ::: "memory")
#define CPWAIT0()  asm volatile("cp.async.wait_group 0;" ::: "memory")

__device__ __forceinline__ void mma16816(float* d, const uint32_t* a, const uint32_t* b) {
    asm volatile(
        "mma.sync.aligned.m16n8k16.row.col.f32.f16.f16.f32 "
        "{%0,%1,%2,%3}, {%4,%5,%6,%7}, {%8,%9}, {%0,%1,%2,%3};"
        : "+f"(d[0]), "+f"(d[1]), "+f"(d[2]), "+f"(d[3])
        : "r"(a[0]), "r"(a[1]), "r"(a[2]), "r"(a[3]), "r"(b[0]), "r"(b[1]));
}

__device__ __forceinline__ uint32_t packh2(float a0, float a1) {
    uint32_t r;
    asm("cvt.rn.f16x2.f32 %0, %1, %2;" : "=r"(r) : "f"(a1), "f"(a0));
    return r;
}

// 16 fp32 -> 2 swizzled 16B fp16 chunks
__device__ __forceinline__ void cvt16_one(const float4* __restrict__ g,
                                          char* row, uint32_t coff, uint32_t rx) {
    uint32_t H[8];
#pragma unroll
    for (int m = 0; m < 4; m++) {
        float4 x = g[m];
        H[2*m]   = packh2(x.x, x.y);
        H[2*m+1] = packh2(x.z, x.w);
    }
#pragma unroll
    for (int h2 = 0; h2 < 2; h2++) {
        uint32_t s = (coff + h2 * 16) ^ rx;
        *(uint4*)(row + s) = make_uint4(H[4*h2], H[4*h2+1], H[4*h2+2], H[4*h2+3]);
    }
}

// ---------------------------------------------------------------------------
// Merged convert + compact. grid (32, BB, 2), 256 threads, 4 threads per row.
__global__ void __launch_bounds__(256)
convert_qkv(const float* __restrict__ Qg, const float* __restrict__ Kg,
            const float* __restrict__ Vg, const int* __restrict__ mask)
{
    const int b = blockIdx.y;
    const int t = threadIdx.x;

    if (blockIdx.z == 0) {
        const int r = blockIdx.x * 64 + (t >> 2);
        const uint32_t q = (uint32_t)(t & 3);
        const uint32_t rx = ((uint32_t)r & 7) << 4;
        const float4* src = (const float4*)(Qg + ((size_t)b * SQ + r) * DD) + q * 4;
        cvt16_one(src, g_qh + ((size_t)b * SQ + r) * 128, q * 32, rx);
        return;
    }

    // ---- z == 1: shuffle scan + gather ----
    __shared__ int swsum[8];
    __shared__ int spfx[256];
    __shared__ int stotal;
    __shared__ int sidx[64];             // slot -> original column, this block's range
    const int* mb = mask + b * SK;
    const int lane = t & 31, wid = t >> 5;

    int v[8], c = 0;
#pragma unroll
    for (int j = 0; j < 8; j++) { v[j] = mb[t * 8 + j]; c += v[j]; }

    int sc = c;                          // warp inclusive scan
#pragma unroll
    for (int off = 1; off < 32; off <<= 1) {
        int o = __shfl_up_sync(0xffffffffu, sc, off);
        if (lane >= off) sc += o;
    }
    if (lane == 31) swsum[wid] = sc;
    __syncthreads();
    if (t == 0) {
        int a = 0;
#pragma unroll
        for (int wdx = 0; wdx < 8; wdx++) { int tmp = swsum[wdx]; swsum[wdx] = a; a += tmp; }
        stotal = a;
    }
    __syncthreads();
    const int p0 = swsum[wid] + sc - c;  // exclusive prefix at column 8t
    spfx[t] = p0;
    const int total = stotal;
    const int base  = blockIdx.x * 64;
    {
        int p = p0;
#pragma unroll
        for (int j = 0; j < 8; j++)
            if (v[j]) {
                if (p >= base && p < base + 64) sidx[p - base] = t * 8 + j;
                p++;
            }
    }
    if (blockIdx.x == 0) {
        if (t == 0) g_cnt[b] = total;
        if (t < 64) {
            uint32_t bits = 0;
            const int* mw = mb + t * 32;
#pragma unroll
            for (int j = 0; j < 32; j++) bits |= (uint32_t)(mw[j] & 1) << j;
            g_mbits[b * 64 + t] = bits;
        }
    }
    __syncthreads();
    if (blockIdx.x == 0 && t < 64) g_cpf[b * 64 + t] = spfx[4 * t];

    const int padded = (total + 63) & ~63;
    const int s = base + (t >> 2);       // compact slot for this thread quad
    if (s >= padded) return;
    const uint32_t q = (uint32_t)(t & 3);
    const uint32_t rx = ((uint32_t)s & 7) << 4;
    char* kH = g_kh + ((size_t)b * SK + s) * 128;
    char* vH = g_vh + ((size_t)b * SK + s) * 128;
    if (s < total) {
        int row = sidx[t >> 2];
        const float4* ks = (const float4*)(Kg + ((size_t)b * SK + row) * DD) + q * 4;
        const float4* vs = (const float4*)(Vg + ((size_t)b * SK + row) * DD) + q * 4;
        cvt16_one(ks, kH, q * 32, rx);
        cvt16_one(vs, vH, q * 32, rx);
    } else {
        // padded slot: zero K and V rows => s = 0, e = 1, PV term = 0
        uint4 z = make_uint4(0, 0, 0, 0);
        uint32_t o0 = (q * 32)      ^ rx;
        uint32_t o1 = (q * 32 + 16) ^ rx;
        *(uint4*)(kH + o0) = z; *(uint4*)(kH + o1) = z;
        *(uint4*)(vH + o0) = z; *(uint4*)(vH + o1) = z;
    }
}

// ---------------------------------------------------------------------------
__device__ __forceinline__ void issue_tile(uint32_t sbase, int b, int i, int tid) {
    uint32_t st = sbase + SM_ST0 + (uint32_t)(i % NSTAGE) * ST_SZ + (uint32_t)tid * 32;
    size_t gb = ((size_t)b * SK + (size_t)i * KTILE) * 128 + (size_t)tid * 32;
    CPA16(st + ST_K,      g_kh + gb);
    CPA16(st + ST_K + 16, g_kh + gb + 16);
    CPA16(st + ST_V,      g_vh + gb);
    CPA16(st + ST_V + 16, g_vh + gb + 16);
}

__global__ void __launch_bounds__(256, 2)
attn_fwd_mma(float* __restrict__ outg)
{
    extern __shared__ char smem[];
    const int b   = blockIdx.y;
    const int qb  = blockIdx.x;
    const int q0  = qb * QTILE;
    const int tid = threadIdx.x;
    const int lane = tid & 31, w = tid >> 5;
    const uint32_t sbase = (uint32_t)__cvta_generic_to_shared(smem);

    const int nk = g_cnt[b];
    const int nt = (nk + KTILE - 1) / KTILE;

    // ---- prologue: Q tile + first two K/V tiles via cp.async ----
    {
        const char* qh = g_qh + ((size_t)b * SQ + q0) * 128 + (size_t)tid * 64;
        uint32_t dh = sbase + SM_Q + (uint32_t)tid * 64;
#pragma unroll
        for (int j = 0; j < 4; j++)
            CPA16(dh + j * 16, qh + j * 16);
        issue_tile(sbase, b, 0, tid);
        CPCOMMIT();                                  // group 0: Q + tile 0
        if (nt > 1) { issue_tile(sbase, b, 1, tid); CPCOMMIT(); }   // group 1
    }

    // per-thread fragment geometry (X4 loads fetch two n-fragments at once)
    const uint32_t sx    = (uint32_t)(lane & 7) << 4;
    const uint32_t offQ  = (16*w + (lane & 15)) * 128 + ((lane >> 4) & 1) * 16;
    const uint32_t offK4 = (lane & 7) * 128 + ((lane >> 3) & 1) * 16
                         + ((lane >> 4) & 1) * 1024;                    // + np*2048 + ks*32
    const uint32_t offV4 = ((lane & 7) + ((lane >> 3) & 1) * 8) * 128
                         + ((lane >> 4) & 1) * 16;                      // + ks*2048 + np*32

    // ---- hoist Q fragments: loop-invariant, loaded once ----
    uint32_t qreg[16];
    {
        if (nt > 1) { CPWAIT1(); } else { CPWAIT0(); }   // group 0 (Q + tile0) resident
        __syncthreads();
#pragma unroll
        for (int ks = 0; ks < 4; ks++)
            LDSM_X4(qreg + 4*ks, sbase + SM_Q + ((offQ + ks * 32) ^ sx));
    }

    float oacc[8][4];
#pragma unroll
    for (int n = 0; n < 8; n++)
#pragma unroll
        for (int j = 0; j < 4; j++) oacc[n][j] = 0.f;
    float rs0 = 0.f, rs1 = 0.f;

    const int rowl = w * 16 + (lane >> 2);
    // fragment-order e output: coalesced uint2 per (i, n, lane)
    uint2* ecw = (uint2*)g_ecomp + (((size_t)(b * 16 + qb)) << 16) + lane;
    const float CEXP = 0.18033688011112042f;   // (1/8) * log2(e)

    for (int i = 0; i < nt; i++) {
        if (i + 1 < nt) { CPWAIT1(); } else { CPWAIT0(); }   // tile i resident
        __syncthreads();      // whole CTA coherent; slot (i+2)%3 fully consumed
        if (i + 2 < nt) { issue_tile(sbase, b, i + 2, tid); CPCOMMIT(); }

        const uint32_t st = sbase + SM_ST0 + (uint32_t)(i % NSTAGE) * ST_SZ;
        uint2* ecwt = ecw + (((uint32_t)i * 8 + w) << 8);   // + (n << 5)

        // ---- S = Q K^T : single fp16, Q from registers ----
        float sacc[8][4];
#pragma unroll
        for (int n = 0; n < 8; n++)
#pragma unroll
            for (int j = 0; j < 4; j++) sacc[n][j] = 0.f;

#pragma unroll
        for (int ks = 0; ks < 4; ks++) {
            uint32_t bk[16];
#pragma unroll
            for (int np = 0; np < 4; np++) {
                uint32_t koff = ((offK4 + (uint32_t)np * 2048 + ks * 32) ^ sx);
                LDSM_X4(bk + 4*np, st + ST_K + koff);
            }
#pragma unroll
            for (int np = 0; np < 4; np++) {
                mma16816(sacc[2*np],     qreg + 4*ks, bk + 4*np);
                mma16816(sacc[2*np + 1], qreg + 4*ks, bk + 4*np + 2);
            }
        }

        // ---- fused exp + fragment-order e store + P V (NO masks: padding
        //      contributes e=1 to rs, corrected in epilogue; PV term is 0) ----
#pragma unroll
        for (int ks = 0; ks < 4; ks++) {
            uint32_t ah[4];
#pragma unroll
            for (int h2 = 0; h2 < 2; h2++) {
                const int n = 2 * ks + h2;
                float e0, e1, e2, e3;
                asm("ex2.approx.ftz.f32 %0, %1;" : "=f"(e0) : "f"(sacc[n][0] * CEXP));
                asm("ex2.approx.ftz.f32 %0, %1;" : "=f"(e1) : "f"(sacc[n][1] * CEXP));
                asm("ex2.approx.ftz.f32 %0, %1;" : "=f"(e2) : "f"(sacc[n][2] * CEXP));
                asm("ex2.approx.ftz.f32 %0, %1;" : "=f"(e3) : "f"(sacc[n][3] * CEXP));
                rs0 += e0 + e1; rs1 += e2 + e3;
                ah[2*h2]     = packh2(e0, e1);
                ah[2*h2 + 1] = packh2(e2, e3);
                ecwt[n << 5] = make_uint2(ah[2*h2], ah[2*h2 + 1]);
            }
#pragma unroll
            for (int np = 0; np < 4; np++) {
                uint32_t bv[4];
                uint32_t voff = ((offV4 + (uint32_t)ks * 2048 + np * 32) ^ sx);
                LDSM_X4T(bv, st + ST_V + voff);
                mma16816(oacc[2*np],     ah, bv);
                mma16816(oacc[2*np + 1], ah, bv + 2);
            }
        }
    }

    // ---- epilogue: correct rowsum for padded e=1 slots, reduce, write ----
    {
        const int qc = lane & 3;
        int cnt = 0;
        for (int s = nk; s < nt * KTILE; s++)
            cnt += (int)(((s & 7) >> 1) == qc);
        rs0 -= (float)cnt;
        rs1 -= (float)cnt;
    }
    rs0 += __shfl_xor_sync(0xffffffffu, rs0, 1);
    rs0 += __shfl_xor_sync(0xffffffffu, rs0, 2);
    rs1 += __shfl_xor_sync(0xffffffffu, rs1, 1);
    rs1 += __shfl_xor_sync(0xffffffffu, rs1, 2);
    float r0 = 1.f / rs0, r1 = 1.f / rs1;

    if ((lane & 3) == 0) {
        g_recip[b * SQ + q0 + rowl]     = r0;
        g_recip[b * SQ + q0 + rowl + 8] = r1;
    }

    float* orow0 = outg + ((size_t)b * SQ + q0 + rowl) * DD + 2 * (lane & 3);
    float* orow1 = orow0 + 8 * DD;
#pragma unroll
    for (int n = 0; n < 8; n++) {
        *(float2*)(orow0 + 8 * n) = make_float2(oacc[n][0] * r0, oacc[n][1] * r0);
        *(float2*)(orow1 + 8 * n) = make_float2(oacc[n][2] * r1, oacc[n][3] * r1);
    }
}

// ---------------------------------------------------------------------------
// Expand fragment-order compact fp16 e -> final fp32 attn.
// One CTA per (b, qblk, w, lane-half): 8 rows = w*16 + lqh*4 + {0..3} + 8g.
#define SE_PITCH (SK + 8)    // +16B pad: lql rows land on distinct banks
__global__ void __launch_bounds__(512)
norm_expand(float* __restrict__ attn)
{
    __shared__ __align__(16) __half se[8 * SE_PITCH];
    __shared__ uint32_t sbits[64];
    __shared__ int      scpf[64];
    __shared__ float    sr[8];

    const int beta = blockIdx.x;
    const int b   = beta >> 8;
    const int qb  = (beta >> 4) & 15;
    const int w   = (beta >> 1) & 7;
    const int lqh = beta & 1;
    const int t = threadIdx.x;

    const int nk = g_cnt[b];
    const int nt = (nk + 63) >> 6;
    const uint2* ecb = (const uint2*)g_ecomp + (((size_t)(b * 16 + qb)) << 16);

    // ---- stage: de-permute fragment blocks into row-major smem ----
    for (int flat = t; flat < nt * 64; flat += 512) {
        int i = flat >> 6, rem = flat & 63, n = rem >> 3, q8 = rem & 7;
        uint4 v = *(const uint4*)(ecb + ((((i*8 + w)*8 + n) << 5) + lqh*16 + 2*q8));
        int lql = q8 >> 1;
        int c = i * 64 + n * 8 + 4 * (q8 & 1);
        *(uint2*)&se[lql * SE_PITCH + c]       = make_uint2(v.x, v.z);   // g=0 row
        *(uint2*)&se[(lql + 4) * SE_PITCH + c] = make_uint2(v.y, v.w);   // g=1 row
    }
    if (t < 64) { sbits[t] = g_mbits[b * 64 + t]; scpf[t] = g_cpf[b * 64 + t]; }
    if (t < 8)
        sr[t] = g_recip[b * SQ + qb * 128 + w * 16 + lqh * 4 + (t & 3) + 8 * (t >> 2)];
    __syncthreads();

    const int wrd = t >> 3;                       // (4t) >> 5
    const int off = (t << 2) & 31;
    const uint32_t bits = sbits[wrd];
    const int slot0 = scpf[wrd] + __popc(bits & ((1u << off) - 1u));
    const int m0 = (int)((bits >> off)     & 1u);
    const int m1 = (int)((bits >> (off+1)) & 1u);
    const int m2 = (int)((bits >> (off+2)) & 1u);
    const int m3 = (int)((bits >> (off+3)) & 1u);

    const size_t rowbase = (size_t)b * SQ + qb * 128 + w * 16 + lqh * 4;
#pragma unroll
    for (int rr = 0; rr < 8; rr++) {
        const __half* crow = se + rr * SE_PITCH;
        const float r = sr[rr];
        float* arow = attn + (rowbase + (rr & 3) + 8 * (rr >> 2)) * SK + (t << 2);
        int slot = slot0;
        float v0 = m0 ? __half2float(crow[slot]) * r : 0.f; slot += m0;
        float v1 = m1 ? __half2float(crow[slot]) * r : 0.f; slot += m1;
        float v2 = m2 ? __half2float(crow[slot]) * r : 0.f; slot += m2;
        float v3 = m3 ? __half2float(crow[slot]) * r : 0.f;
        *(float4*)arow = make_float4(v0, v1, v2, v3);
    }
}

// ---------------------------------------------------------------------------
extern "C" void kernel_launch(void* const* d_in, const int* in_sizes, int n_in,
                              void* d_out, int out_size)
{
    const float* Q    = (const float*)d_in[0];
    const float* K    = (const float*)d_in[1];
    const float* V    = (const float*)d_in[2];
    const int*   mask = (const int*)d_in[3];

    float* out  = (float*)d_out;
    float* attn = out + (size_t)BB * SQ * DD;

    cudaFuncSetAttribute(attn_fwd_mma, cudaFuncAttributeMaxDynamicSharedMemorySize, SMEM_TOTAL);

    convert_qkv<<<dim3(32, BB, 2), 256>>>(Q, K, V, mask);   // pos 0
    dim3 grid(SQ / QTILE, BB);
    attn_fwd_mma<<<grid, 256, SMEM_TOTAL>>>(out);           // pos 1
    norm_expand<<<BB * 16 * 8 * 2, 512>>>(attn);            // pos 2
}

// round 17
// speedup vs baseline: 1.0074x; 1.0074x over previous
#include <cuda_runtime.h>
#include <cuda_fp16.h>
#include <cstdint>

#define BB 16
#define SQ 2048
#define SK 2048
#define DD 64

#define QTILE 128
#define KTILE 64

// ---- smem layout (bytes) ----
#define SM_Q    0
#define SM_ST0  16384
#define ST_K    0
#define ST_V    8192
#define ST_SZ   16384
#define NSTAGE  3
#define SMEM_TOTAL (SM_ST0 + NSTAGE*ST_SZ)   // 65536

__device__ float    g_recip[BB * SQ];
__device__ int      g_cnt[BB];
__device__ uint32_t g_mbits[BB * 64];
__device__ int      g_cpf[BB * 64];
// unnormalized e (fp16) in MMA-FRAGMENT order (padded slots hold 1.0, never read):
// per (b, qblk): 65536 uint2; index = ((i*8 + w)*8 + n)*32 + lane
__device__ __half   g_ecomp[(size_t)BB * SQ * SK];
// pre-swizzled fp16 K/V (128B/row), compact slot order; padded slots ZEROED.
__device__ char g_kh[(size_t)BB * SK * 128], g_vh[(size_t)BB * SK * 128];

// ---------------------------------------------------------------------------
#define LDSM_X4(R, addr) \
    asm volatile("ldmatrix.sync.aligned.m8n8.x4.shared.b16 {%0,%1,%2,%3}, [%4];" \
        : "=r"((R)[0]), "=r"((R)[1]), "=r"((R)[2]), "=r"((R)[3]) : "r"(addr))
#define LDSM_X4T(R, addr) \
    asm volatile("ldmatrix.sync.aligned.m8n8.x4.trans.shared.b16 {%0,%1,%2,%3}, [%4];" \
        : "=r"((R)[0]), "=r"((R)[1]), "=r"((R)[2]), "=r"((R)[3]) : "r"(addr))

#define CPA16(dst, src) \
    asm volatile("cp.async.cg.shared.global [%0], [%1], 16;" :: "r"(dst), "l"(src))
#define CPCOMMIT() asm volatile("cp.async.commit_group;" ::: "memory")
#define CPWAIT1()  asm volatile("cp.async.wait_group 1;" ::: "memory")
#define CPWAIT0()  asm volatile("cp.async.wait_group 0;" ::: "memory")

// streaming (evict-first) stores / loads for write-once / read-once data
#define STG_CS_V2(addr, x, y) \
    asm volatile("st.global.cs.v2.u32 [%0], {%1, %2};" :: "l"(addr), "r"(x), "r"(y) : "memory")
#define STG_CS_V4F(addr, a, b, c, d) \
    asm volatile("st.global.cs.v4.f32 [%0], {%1, %2, %3, %4};" \
        :: "l"(addr), "f"(a), "f"(b), "f"(c), "f"(d) : "memory")
#define LDG_CS_V4(v, addr) \
    asm volatile("ld.global.cs.v4.u32 {%0, %1, %2, %3}, [%4];" \
        : "=r"((v).x), "=r"((v).y), "=r"((v).z), "=r"((v).w) : "l"(addr))

__device__ __forceinline__ void mma16816(float* d, const uint32_t* a, const uint32_t* b) {
    asm volatile(
        "mma.sync.aligned.m16n8k16.row.col.f32.f16.f16.f32 "
        "{%0,%1,%2,%3}, {%4,%5,%6,%7}, {%8,%9}, {%0,%1,%2,%3};"
        : "+f"(d[0]), "+f"(d[1]), "+f"(d[2]), "+f"(d[3])
        : "r"(a[0]), "r"(a[1]), "r"(a[2]), "r"(a[3]), "r"(b[0]), "r"(b[1]));
}

__device__ __forceinline__ uint32_t packh2(float a0, float a1) {
    uint32_t r;
    asm("cvt.rn.f16x2.f32 %0, %1, %2;" : "=r"(r) : "f"(a1), "f"(a0));
    return r;
}

// 16 fp32 -> 2 swizzled 16B fp16 chunks
__device__ __forceinline__ void cvt16_one(const float4* __restrict__ g,
                                          char* row, uint32_t coff, uint32_t rx) {
    uint32_t H[8];
#pragma unroll
    for (int m = 0; m < 4; m++) {
        float4 x = g[m];
        H[2*m]   = packh2(x.x, x.y);
        H[2*m+1] = packh2(x.z, x.w);
    }
#pragma unroll
    for (int h2 = 0; h2 < 2; h2++) {
        uint32_t s = (coff + h2 * 16) ^ rx;
        *(uint4*)(row + s) = make_uint4(H[4*h2], H[4*h2+1], H[4*h2+2], H[4*h2+3]);
    }
}

// 8 fp32 -> 1 swizzled 16B fp16 chunk
__device__ __forceinline__ void cvt8_one(const float4* __restrict__ g,
                                         char* row, uint32_t coff, uint32_t rx) {
    float4 x0 = g[0], x1 = g[1];
    *(uint4*)(row + (coff ^ rx)) = make_uint4(
        packh2(x0.x, x0.y), packh2(x0.z, x0.w),
        packh2(x1.x, x1.y), packh2(x1.z, x1.w));
}

// ---------------------------------------------------------------------------
// Compact + K/V convert. grid (64, BB), 256 threads, 8 threads per slot
// (32 slots per CTA). xblk==0 publishes g_cnt / g_mbits / g_cpf.
__global__ void __launch_bounds__(256)
convert_kv(const float* __restrict__ Kg, const float* __restrict__ Vg,
           const int* __restrict__ mask)
{
    __shared__ int swsum[8];
    __shared__ int spfx[256];
    __shared__ int stotal;
    __shared__ int sidx[32];             // slot -> original column, this block's range
    const int b = blockIdx.y;
    const int t = threadIdx.x;
    const int* mb = mask + b * SK;
    const int lane = t & 31, wid = t >> 5;

    int v[8], c = 0;
#pragma unroll
    for (int j = 0; j < 8; j++) { v[j] = mb[t * 8 + j]; c += v[j]; }

    int sc = c;                          // warp inclusive scan
#pragma unroll
    for (int off = 1; off < 32; off <<= 1) {
        int o = __shfl_up_sync(0xffffffffu, sc, off);
        if (lane >= off) sc += o;
    }
    if (lane == 31) swsum[wid] = sc;
    __syncthreads();
    if (t == 0) {
        int a = 0;
#pragma unroll
        for (int wdx = 0; wdx < 8; wdx++) { int tmp = swsum[wdx]; swsum[wdx] = a; a += tmp; }
        stotal = a;
    }
    __syncthreads();
    const int p0 = swsum[wid] + sc - c;  // exclusive prefix at column 8t
    spfx[t] = p0;
    const int total = stotal;
    const int base  = blockIdx.x * 32;
    {
        int p = p0;
#pragma unroll
        for (int j = 0; j < 8; j++)
            if (v[j]) {
                if (p >= base && p < base + 32) sidx[p - base] = t * 8 + j;
                p++;
            }
    }
    if (blockIdx.x == 0) {
        if (t == 0) g_cnt[b] = total;
        if (t < 64) {
            uint32_t bits = 0;
            const int* mw = mb + t * 32;
#pragma unroll
            for (int j = 0; j < 32; j++) bits |= (uint32_t)(mw[j] & 1) << j;
            g_mbits[b * 64 + t] = bits;
        }
    }
    __syncthreads();
    if (blockIdx.x == 0 && t < 64) g_cpf[b * 64 + t] = spfx[4 * t];

    const int padded = (total + 63) & ~63;
    const int s = base + (t >> 3);       // compact slot for this thread octet
    if (s >= padded) return;
    const uint32_t q = (uint32_t)(t & 7);        // 16B chunk within row
    const uint32_t rx = ((uint32_t)s & 7) << 4;
    char* kH = g_kh + ((size_t)b * SK + s) * 128;
    char* vH = g_vh + ((size_t)b * SK + s) * 128;
    if (s < total) {
        int row = sidx[t >> 3];
        const float4* ks = (const float4*)(Kg + ((size_t)b * SK + row) * DD) + q * 2;
        const float4* vs = (const float4*)(Vg + ((size_t)b * SK + row) * DD) + q * 2;
        cvt8_one(ks, kH, q * 16, rx);
        cvt8_one(vs, vH, q * 16, rx);
    } else {
        // padded slot: zero K and V rows => s = 0, e = 1, PV term = 0
        uint4 z = make_uint4(0, 0, 0, 0);
        uint32_t o = (q * 16) ^ rx;
        *(uint4*)(kH + o) = z;
        *(uint4*)(vH + o) = z;
    }
}

// ---------------------------------------------------------------------------
__device__ __forceinline__ void issue_tile(uint32_t sbase, int b, int i, int tid) {
    uint32_t st = sbase + SM_ST0 + (uint32_t)(i % NSTAGE) * ST_SZ + (uint32_t)tid * 32;
    size_t gb = ((size_t)b * SK + (size_t)i * KTILE) * 128 + (size_t)tid * 32;
    CPA16(st + ST_K,      g_kh + gb);
    CPA16(st + ST_K + 16, g_kh + gb + 16);
    CPA16(st + ST_V,      g_vh + gb);
    CPA16(st + ST_V + 16, g_vh + gb + 16);
}

__global__ void __launch_bounds__(256, 2)
attn_fwd_mma(const float* __restrict__ Qg, float* __restrict__ outg)
{
    extern __shared__ char smem[];
    const int b   = blockIdx.y;
    const int qb  = blockIdx.x;
    const int q0  = qb * QTILE;
    const int tid = threadIdx.x;
    const int lane = tid & 31, w = tid >> 5;
    const uint32_t sbase = (uint32_t)__cvta_generic_to_shared(smem);

    const int nk = g_cnt[b];
    const int nt = (nk + KTILE - 1) / KTILE;

    // ---- prologue: issue K/V tiles 0,1 (async), then convert our Q tile
    //      fp32 -> fp16 directly into smem (overlaps the cp.async) ----
    {
        issue_tile(sbase, b, 0, tid);
        CPCOMMIT();                                  // group 0: tile 0
        if (nt > 1) { issue_tile(sbase, b, 1, tid); CPCOMMIT(); }   // group 1

        const int r = tid >> 1, h = tid & 1;         // row 0..127, half 0..1
        const float4* src = (const float4*)(Qg + ((size_t)b * SQ + q0 + r) * DD) + h * 8;
        char* qrow = smem + SM_Q + r * 128;
        const uint32_t rx = ((uint32_t)r & 7) << 4;
        cvt16_one(src,     qrow, h * 64,      rx);
        cvt16_one(src + 4, qrow, h * 64 + 32, rx);
    }

    // per-thread fragment geometry (X4 loads fetch two n-fragments at once)
    const uint32_t sx    = (uint32_t)(lane & 7) << 4;
    const uint32_t offQ  = (16*w + (lane & 15)) * 128 + ((lane >> 4) & 1) * 16;
    const uint32_t offK4 = (lane & 7) * 128 + ((lane >> 3) & 1) * 16
                         + ((lane >> 4) & 1) * 1024;                    // + np*2048 + ks*32
    const uint32_t offV4 = ((lane & 7) + ((lane >> 3) & 1) * 8) * 128
                         + ((lane >> 4) & 1) * 16;                      // + ks*2048 + np*32

    // ---- hoist Q fragments: loop-invariant, loaded once ----
    uint32_t qreg[16];
    {
        if (nt > 1) { CPWAIT1(); } else { CPWAIT0(); }   // tile 0 resident
        __syncthreads();                                 // Q STS visible CTA-wide
#pragma unroll
        for (int ks = 0; ks < 4; ks++)
            LDSM_X4(qreg + 4*ks, sbase + SM_Q + ((offQ + ks * 32) ^ sx));
    }

    float oacc[8][4];
#pragma unroll
    for (int n = 0; n < 8; n++)
#pragma unroll
        for (int j = 0; j < 4; j++) oacc[n][j] = 0.f;
    float rs0 = 0.f, rs1 = 0.f;

    const int rowl = w * 16 + (lane >> 2);
    // fragment-order e output: coalesced uint2 per (i, n, lane)
    uint2* ecw = (uint2*)g_ecomp + (((size_t)(b * 16 + qb)) << 16) + lane;
    const float CEXP = 0.18033688011112042f;   // (1/8) * log2(e)

    for (int i = 0; i < nt; i++) {
        if (i + 1 < nt) { CPWAIT1(); } else { CPWAIT0(); }   // tile i resident
        __syncthreads();      // whole CTA coherent; slot (i+2)%3 fully consumed
        if (i + 2 < nt) { issue_tile(sbase, b, i + 2, tid); CPCOMMIT(); }

        const uint32_t st = sbase + SM_ST0 + (uint32_t)(i % NSTAGE) * ST_SZ;
        uint2* ecwt = ecw + (((uint32_t)i * 8 + w) << 8);   // + (n << 5)

        // ---- S = Q K^T : single fp16, Q from registers ----
        float sacc[8][4];
#pragma unroll
        for (int n = 0; n < 8; n++)
#pragma unroll
            for (int j = 0; j < 4; j++) sacc[n][j] = 0.f;

#pragma unroll
        for (int ks = 0; ks < 4; ks++) {
            uint32_t bk[16];
#pragma unroll
            for (int np = 0; np < 4; np++) {
                uint32_t koff = ((offK4 + (uint32_t)np * 2048 + ks * 32) ^ sx);
                LDSM_X4(bk + 4*np, st + ST_K + koff);
            }
#pragma unroll
            for (int np = 0; np < 4; np++) {
                mma16816(sacc[2*np],     qreg + 4*ks, bk + 4*np);
                mma16816(sacc[2*np + 1], qreg + 4*ks, bk + 4*np + 2);
            }
        }

        // ---- fused exp + fragment-order e store (.cs) + P V ----
#pragma unroll
        for (int ks = 0; ks < 4; ks++) {
            uint32_t ah[4];
#pragma unroll
            for (int h2 = 0; h2 < 2; h2++) {
                const int n = 2 * ks + h2;
                float e0, e1, e2, e3;
                asm("ex2.approx.ftz.f32 %0, %1;" : "=f"(e0) : "f"(sacc[n][0] * CEXP));
                asm("ex2.approx.ftz.f32 %0, %1;" : "=f"(e1) : "f"(sacc[n][1] * CEXP));
                asm("ex2.approx.ftz.f32 %0, %1;" : "=f"(e2) : "f"(sacc[n][2] * CEXP));
                asm("ex2.approx.ftz.f32 %0, %1;" : "=f"(e3) : "f"(sacc[n][3] * CEXP));
                rs0 += e0 + e1; rs1 += e2 + e3;
                ah[2*h2]     = packh2(e0, e1);
                ah[2*h2 + 1] = packh2(e2, e3);
                STG_CS_V2(ecwt + (n << 5), ah[2*h2], ah[2*h2 + 1]);
            }
#pragma unroll
            for (int np = 0; np < 4; np++) {
                uint32_t bv[4];
                uint32_t voff = ((offV4 + (uint32_t)ks * 2048 + np * 32) ^ sx);
                LDSM_X4T(bv, st + ST_V + voff);
                mma16816(oacc[2*np],     ah, bv);
                mma16816(oacc[2*np + 1], ah, bv + 2);
            }
        }
    }

    // ---- epilogue: correct rowsum for padded e=1 slots, reduce, write ----
    {
        const int qc = lane & 3;
        int cnt = 0;
        for (int s = nk; s < nt * KTILE; s++)
            cnt += (int)(((s & 7) >> 1) == qc);
        rs0 -= (float)cnt;
        rs1 -= (float)cnt;
    }
    rs0 += __shfl_xor_sync(0xffffffffu, rs0, 1);
    rs0 += __shfl_xor_sync(0xffffffffu, rs0, 2);
    rs1 += __shfl_xor_sync(0xffffffffu, rs1, 1);
    rs1 += __shfl_xor_sync(0xffffffffu, rs1, 2);
    float r0 = 1.f / rs0, r1 = 1.f / rs1;

    if ((lane & 3) == 0) {
        g_recip[b * SQ + q0 + rowl]     = r0;
        g_recip[b * SQ + q0 + rowl + 8] = r1;
    }

    float* orow0 = outg + ((size_t)b * SQ + q0 + rowl) * DD + 2 * (lane & 3);
    float* orow1 = orow0 + 8 * DD;
#pragma unroll
    for (int n = 0; n < 8; n++) {
        *(float2*)(orow0 + 8 * n) = make_float2(oacc[n][0] * r0, oacc[n][1] * r0);
        *(float2*)(orow1 + 8 * n) = make_float2(oacc[n][2] * r1, oacc[n][3] * r1);
    }
}

// ---------------------------------------------------------------------------
// Expand fragment-order compact fp16 e -> final fp32 attn.
// One CTA per (b, qblk, w, lane-half): 8 rows = w*16 + lqh*4 + {0..3} + 8g.
// Streaming loads/stores: this pass's data is read-once / write-once.
#define SE_PITCH (SK + 8)    // +16B pad: lql rows land on distinct banks
__global__ void __launch_bounds__(512)
norm_expand(float* __restrict__ attn)
{
    __shared__ __align__(16) __half se[8 * SE_PITCH];
    __shared__ uint32_t sbits[64];
    __shared__ int      scpf[64];
    __shared__ float    sr[8];

    const int beta = blockIdx.x;
    const int b   = beta >> 8;
    const int qb  = (beta >> 4) & 15;
    const int w   = (beta >> 1) & 7;
    const int lqh = beta & 1;
    const int t = threadIdx.x;

    const int nk = g_cnt[b];
    const int nt = (nk + 63) >> 6;
    const uint2* ecb = (const uint2*)g_ecomp + (((size_t)(b * 16 + qb)) << 16);

    // ---- stage: de-permute fragment blocks into row-major smem ----
    for (int flat = t; flat < nt * 64; flat += 512) {
        int i = flat >> 6, rem = flat & 63, n = rem >> 3, q8 = rem & 7;
        uint4 v;
        LDG_CS_V4(v, ecb + ((((i*8 + w)*8 + n) << 5) + lqh*16 + 2*q8));
        int lql = q8 >> 1;
        int c = i * 64 + n * 8 + 4 * (q8 & 1);
        *(uint2*)&se[lql * SE_PITCH + c]       = make_uint2(v.x, v.z);   // g=0 row
        *(uint2*)&se[(lql + 4) * SE_PITCH + c] = make_uint2(v.y, v.w);   // g=1 row
    }
    if (t < 64) { sbits[t] = g_mbits[b * 64 + t]; scpf[t] = g_cpf[b * 64 + t]; }
    if (t < 8)
        sr[t] = g_recip[b * SQ + qb * 128 + w * 16 + lqh * 4 + (t & 3) + 8 * (t >> 2)];
    __syncthreads();

    const int wrd = t >> 3;                       // (4t) >> 5
    const int off = (t << 2) & 31;
    const uint32_t bits = sbits[wrd];
    const int slot0 = scpf[wrd] + __popc(bits & ((1u << off) - 1u));
    const int m0 = (int)((bits >> off)     & 1u);
    const int m1 = (int)((bits >> (off+1)) & 1u);
    const int m2 = (int)((bits >> (off+2)) & 1u);
    const int m3 = (int)((bits >> (off+3)) & 1u);

    const size_t rowbase = (size_t)b * SQ + qb * 128 + w * 16 + lqh * 4;
#pragma unroll
    for (int rr = 0; rr < 8; rr++) {
        const __half* crow = se + rr * SE_PITCH;
        const float r = sr[rr];
        float* arow = attn + (rowbase + (rr & 3) + 8 * (rr >> 2)) * SK + (t << 2);
        int slot = slot0;
        float v0 = m0 ? __half2float(crow[slot]) * r : 0.f; slot += m0;
        float v1 = m1 ? __half2float(crow[slot]) * r : 0.f; slot += m1;
        float v2 = m2 ? __half2float(crow[slot]) * r : 0.f; slot += m2;
        float v3 = m3 ? __half2float(crow[slot]) * r : 0.f;
        STG_CS_V4F(arow, v0, v1, v2, v3);
    }
}

// ---------------------------------------------------------------------------
extern "C" void kernel_launch(void* const* d_in, const int* in_sizes, int n_in,
                              void* d_out, int out_size)
{
    const float* Q    = (const float*)d_in[0];
    const float* K    = (const float*)d_in[1];
    const float* V    = (const float*)d_in[2];
    const int*   mask = (const int*)d_in[3];

    float* out  = (float*)d_out;
    float* attn = out + (size_t)BB * SQ * DD;

    cudaFuncSetAttribute(attn_fwd_mma, cudaFuncAttributeMaxDynamicSharedMemorySize, SMEM_TOTAL);

    convert_kv<<<dim3(64, BB), 256>>>(K, V, mask);          // pos 0
    dim3 grid(SQ / QTILE, BB);
    attn_fwd_mma<<<grid, 256, SMEM_TOTAL>>>(Q, out);        // pos 1
    norm_expand<<<BB * 16 * 8 * 2, 512>>>(attn);            // pos 2
}